// round 3
// baseline (speedup 1.0000x reference)
#include <cuda_runtime.h>
#include <cuda_bf16.h>
#include <cstddef>

#define HD   512
#define VOC  32000
#define TT1  128
#define TT2  64
#define NB   32
#define H3   1536
#define BHD  (NB*HD)
#define YSZ  ((size_t)TT2*NB*VOC)
#define HF_OFF YSZ
#define LS_OFF (YSZ + (size_t)2*BHD)

// ---------------- scratch (device globals; no runtime alloc) ----------------
__device__ float g_X  [TT2*NB*HD];      // embedded tokens
__device__ float g_q  [TT2*NB*HD];      // q_all = X @ Wx^T
__device__ float g_ep [TT1*NB*HD];      // enc_proj
__device__ float g_sc [TT2*TT1*NB];     // softmax scores (t2,t1,b)
__device__ float g_av [TT2*NB*HD];      // att_v_all
__device__ float g_gi0[TT2*NB*H3];      // precomputed GRU0 input gates (incl b_ih0)
__device__ float g_ys [TT2*NB*HD];      // h1 per step
__device__ float g_h0c[2*BHD];          // ping-pong layer-0 hidden (chunk layout)
__device__ float g_h1c[2*BHD];          // ping-pong layer-1 hidden (chunk layout)

// chunk layout: value (b,k) stored at (k>>2)*128 + b*4 + (k&3)
__device__ __forceinline__ int CH(int b, int k){ return ((k>>2)<<7) + (b<<2) + (k&3); }

__device__ __forceinline__ float fast_tanh(float x){
    // 1 - 2/(exp(2x)+1); exact at +-inf, ~1e-6 rel
    float e = __expf(2.f*x);
    return 1.f - __fdividef(2.f, e + 1.f);
}
__device__ __forceinline__ float fast_sig(float x){
    return __fdividef(1.f, 1.f + __expf(-x));
}

// ---------------- embed + state init ----------------
__global__ __launch_bounds__(256) void k_embed(const int* __restrict__ tok,
                                               const float* __restrict__ emb,
                                               const float* __restrict__ state)
{
    int i = blockIdx.x*256 + threadIdx.x;
    if (i < TT2*NB*HD){
        int row = i >> 9;          // t2*NB + b
        int h   = i & (HD-1);
        g_X[i] = emb[(size_t)tok[row]*HD + h];
    }
    if (i < 2*BHD){
        int l = (i >= BHD);
        int r = i & (BHD-1);
        int b = r >> 9, h = r & (HD-1);
        float v = state[i];
        if (l == 0) g_h0c[CH(b,h)] = v;
        else        g_h1c[CH(b,h)] = v;
    }
}

// ---------------- generic 3xTF32 GEMM: C[M,N] = A(M,K) * B(N,K)^T (+bias) (+=C) ----
__device__ __forceinline__ unsigned f2tf(float f){
    unsigned r; asm("cvt.rna.tf32.f32 %0, %1;" : "=r"(r) : "f"(f)); return r;
}
__device__ __forceinline__ void mma8(float* d, const unsigned* a, unsigned b0, unsigned b1){
    asm volatile("mma.sync.aligned.m16n8k8.row.col.f32.tf32.tf32.f32 "
        "{%0,%1,%2,%3}, {%4,%5,%6,%7}, {%8,%9}, {%0,%1,%2,%3};\n"
        : "+f"(d[0]), "+f"(d[1]), "+f"(d[2]), "+f"(d[3])
        : "r"(a[0]), "r"(a[1]), "r"(a[2]), "r"(a[3]), "r"(b0), "r"(b1));
}
#define SKA 68   // padded smem row stride (floats)

__global__ __launch_bounds__(256) void k_gemm3(
    const float* __restrict__ A, int lda,
    const float* __restrict__ Bm, int ldb,
    const float* __restrict__ bias,
    float* __restrict__ C, int ldc,
    int K, int accmode)
{
    __shared__ unsigned sAh[32*SKA], sAl[32*SKA], sBh[32*SKA], sBl[32*SKA];
    const int m0 = blockIdx.y * 64;
    const int n0 = blockIdx.x * 64;
    const int tid  = threadIdx.x;
    const int lane = tid & 31, warp = tid >> 5;
    const int wm = (warp & 3) * 16;
    const int wn = (warp >> 2) * 32;
    const int g  = lane >> 2, tg = lane & 3;

    float acc[4][4];
    #pragma unroll
    for (int i=0;i<4;i++){ acc[i][0]=0.f; acc[i][1]=0.f; acc[i][2]=0.f; acc[i][3]=0.f; }

    for (int k0 = 0; k0 < K; k0 += 32){
        #pragma unroll
        for (int r = 0; r < 2; r++){
            int idx4 = tid*2 + r;                 // 0..511
            int row  = idx4 >> 3;                 // 0..63
            int c4   = (idx4 & 7) * 4;            // k local base
            float4 av = *reinterpret_cast<const float4*>(A  + (size_t)(m0+row)*lda + k0 + c4);
            float4 bv = *reinterpret_cast<const float4*>(Bm + (size_t)(n0+row)*ldb + k0 + c4);
            float aa[4] = {av.x, av.y, av.z, av.w};
            float bb[4] = {bv.x, bv.y, bv.z, bv.w};
            #pragma unroll
            for (int j=0;j<4;j++){
                unsigned h1 = f2tf(aa[j]);
                sAh[(c4+j)*SKA + row] = h1;
                sAl[(c4+j)*SKA + row] = f2tf(aa[j] - __uint_as_float(h1));
                unsigned h2 = f2tf(bb[j]);
                sBh[(c4+j)*SKA + row] = h2;
                sBl[(c4+j)*SKA + row] = f2tf(bb[j] - __uint_as_float(h2));
            }
        }
        __syncthreads();
        #pragma unroll
        for (int kk = 0; kk < 4; kk++){
            const int kb = kk*8;
            unsigned ah[4], al[4];
            ah[0] = sAh[(kb+tg  )*SKA + wm + g    ];
            ah[1] = sAh[(kb+tg  )*SKA + wm + g + 8];
            ah[2] = sAh[(kb+tg+4)*SKA + wm + g    ];
            ah[3] = sAh[(kb+tg+4)*SKA + wm + g + 8];
            al[0] = sAl[(kb+tg  )*SKA + wm + g    ];
            al[1] = sAl[(kb+tg  )*SKA + wm + g + 8];
            al[2] = sAl[(kb+tg+4)*SKA + wm + g    ];
            al[3] = sAl[(kb+tg+4)*SKA + wm + g + 8];
            #pragma unroll
            for (int nt=0; nt<4; nt++){
                const int nn = wn + nt*8 + g;
                unsigned bh0 = sBh[(kb+tg  )*SKA + nn];
                unsigned bh1 = sBh[(kb+tg+4)*SKA + nn];
                unsigned bl0 = sBl[(kb+tg  )*SKA + nn];
                unsigned bl1 = sBl[(kb+tg+4)*SKA + nn];
                mma8(acc[nt], ah, bh0, bh1);   // hi*hi
                mma8(acc[nt], ah, bl0, bl1);   // hi*lo
                mma8(acc[nt], al, bh0, bh1);   // lo*hi
            }
        }
        __syncthreads();
    }
    #pragma unroll
    for (int nt=0; nt<4; nt++){
        int col = n0 + wn + nt*8 + tg*2;
        int r0  = m0 + wm + g;
        float b0v = 0.f, b1v = 0.f;
        if (bias){ b0v = bias[col]; b1v = bias[col+1]; }
        float* p0 = C + (size_t)r0*ldc + col;
        float* p1 = C + (size_t)(r0+8)*ldc + col;
        float c00 = acc[nt][0]+b0v, c01 = acc[nt][1]+b1v;
        float c10 = acc[nt][2]+b0v, c11 = acc[nt][3]+b1v;
        if (accmode){ c00 += p0[0]; c01 += p0[1]; c10 += p1[0]; c11 += p1[1]; }
        p0[0]=c00; p0[1]=c01; p1[0]=c10; p1[1]=c11;
    }
}

// ---------------- attention logits + softmax (t2-group of 8, b) ----------------
__global__ __launch_bounds__(256) void k_att_scores(const float* __restrict__ va,
                                                    float* __restrict__ dout)
{
    __shared__ float q8[8*HD];
    __shared__ float vsm[HD];
    __shared__ float esm[8*TT1];
    const int b   = blockIdx.y;
    const int t2b = blockIdx.x * 8;
    const int tid = threadIdx.x, lane = tid & 31, w = tid >> 5;

    for (int i = tid; i < 8*HD; i += 256){
        int t2i = i >> 9, h = i & (HD-1);
        q8[i] = g_q[((size_t)(t2b + t2i)*NB + b)*HD + h];
    }
    for (int i = tid; i < HD; i += 256) vsm[i] = va[i];
    __syncthreads();

    for (int t1 = w; t1 < TT1; t1 += 8){
        const float* ep = g_ep + ((size_t)t1*NB + b)*HD;
        float accv[8];
        #pragma unroll
        for (int i=0;i<8;i++) accv[i] = 0.f;
        for (int h = lane; h < HD; h += 32){
            float e  = ep[h];
            float vv = vsm[h];
            #pragma unroll
            for (int i=0;i<8;i++) accv[i] += vv * fast_tanh(q8[i*HD + h] + e);
        }
        #pragma unroll
        for (int i=0;i<8;i++){
            float s = accv[i];
            #pragma unroll
            for (int o=16;o;o>>=1) s += __shfl_xor_sync(0xffffffffu, s, o);
            if (lane == 0) esm[i*TT1 + t1] = s;
        }
    }
    __syncthreads();

    // softmax over t1 — warp w owns local t2 = w
    {
        float v[4];
        #pragma unroll
        for (int i=0;i<4;i++) v[i] = esm[w*TT1 + lane + 32*i];
        float m = fmaxf(fmaxf(v[0],v[1]), fmaxf(v[2],v[3]));
        #pragma unroll
        for (int o=16;o;o>>=1) m = fmaxf(m, __shfl_xor_sync(0xffffffffu, m, o));
        float s = 0.f;
        #pragma unroll
        for (int i=0;i<4;i++){ v[i] = __expf(v[i]-m); s += v[i]; }
        #pragma unroll
        for (int o=16;o;o>>=1) s += __shfl_xor_sync(0xffffffffu, s, o);
        float inv = __fdividef(1.f, s);
        int t2 = t2b + w;
        #pragma unroll
        for (int i=0;i<4;i++){
            int t1 = lane + 32*i;
            float sc = v[i]*inv;
            g_sc[((size_t)t2*TT1 + t1)*NB + b] = sc;
            if (t2 == TT2-1) dout[LS_OFF + (size_t)t1*NB + b] = sc;
        }
    }
}

// ---------------- attention values: att_v[t2,b,h] = sum_t1 enc[t1,b,h]*score ----
__global__ __launch_bounds__(256) void k_attv(const float* __restrict__ enc)
{
    __shared__ float sst[TT1*32];    // [t1][t2local]
    const int b   = blockIdx.x;
    const int t2o = blockIdx.y * 32;
    const int h   = blockIdx.z * 256 + threadIdx.x;
    for (int i = threadIdx.x; i < 32*TT1; i += 256){
        int t1 = i >> 5, i2 = i & 31;
        sst[t1*32 + i2] = g_sc[((size_t)(t2o + i2)*TT1 + t1)*NB + b];
    }
    __syncthreads();
    float acc[32];
    #pragma unroll
    for (int i=0;i<32;i++) acc[i] = 0.f;
    for (int t1 = 0; t1 < TT1; t1++){
        float ev = enc[((size_t)t1*NB + b)*HD + h];
        #pragma unroll
        for (int i=0;i<32;i++) acc[i] += ev * sst[t1*32 + i];
    }
    #pragma unroll
    for (int i=0;i<32;i++)
        g_av[((size_t)(t2o+i)*NB + b)*HD + h] = acc[i];
}

// ---------------- combined recurrence step: gru0(t) + gru1(t-1) ----------------
// warp computes 3 row-dots (rows j, j+512, j+1024 of W, ld 512) vs chunked h, lane=b
__device__ __forceinline__ void dot3(const float* __restrict__ W, int j,
                                     const float* __restrict__ hch, int b,
                                     float& s0, float& s1, float& s2)
{
    const float* w0 = W + (size_t) j        *HD;
    const float* w1 = W + (size_t)(j+ 512)  *HD;
    const float* w2 = W + (size_t)(j+1024)  *HD;
    float a0=0.f, a1=0.f, a2=0.f;
    #pragma unroll 4
    for (int k = 0; k < HD; k += 4){
        float4 hv = *reinterpret_cast<const float4*>(hch + ((k>>2)<<7) + (b<<2));
        float4 x = *reinterpret_cast<const float4*>(w0 + k);
        float4 y = *reinterpret_cast<const float4*>(w1 + k);
        float4 z = *reinterpret_cast<const float4*>(w2 + k);
        a0 += x.x*hv.x + x.y*hv.y + x.z*hv.z + x.w*hv.w;
        a1 += y.x*hv.x + y.y*hv.y + y.z*hv.z + y.w*hv.w;
        a2 += z.x*hv.x + z.y*hv.y + z.z*hv.z + z.w*hv.w;
    }
    s0 = a0; s1 = a1; s2 = a2;
}

__global__ __launch_bounds__(256) void k_step(int t,
    const float* __restrict__ W_hh0, const float* __restrict__ b_hh0,
    const float* __restrict__ W_ih1, const float* __restrict__ b_ih1,
    const float* __restrict__ W_hh1, const float* __restrict__ b_hh1)
{
    const int blk  = blockIdx.x;
    const int warp = threadIdx.x >> 5;
    const int b    = threadIdx.x & 31;

    if (blk < 64){
        // ---- gru0 at time t ----
        if (t >= TT2) return;
        const int j = blk*8 + warp;
        const int p = t & 1;
        const float* hch = g_h0c + p*BHD;
        float s0, s1, s2;
        dot3(W_hh0, j, hch, b, s0, s1, s2);
        const float* gi = g_gi0 + ((size_t)t*NB + b)*H3;
        float r = fast_sig (gi[j      ] + s0 + b_hh0[j      ]);
        float z = fast_sig (gi[j+ 512] + s1 + b_hh0[j+ 512]);
        float n = fast_tanh(gi[j+1024] + r*(s2 + b_hh0[j+1024]));
        float hold = hch[CH(b,j)];
        g_h0c[(1-p)*BHD + CH(b,j)] = (1.f-z)*n + z*hold;
    } else {
        // ---- gru1 at time s = t-1 ----
        if (t < 1) return;
        __shared__ float sm[8][3][32];
        const int s    = t - 1;
        const int blk2 = blk - 64;               // 0..127
        const int j    = blk2*4 + (warp >> 1);
        const int mat  = warp & 1;               // 0: W_ih1*h0new, 1: W_hh1*h1old
        const int p1   = s & 1;
        const float* hin = (mat == 0) ? (g_h0c + ((s+1)&1)*BHD)
                                      : (g_h1c + p1*BHD);
        const float* W   = (mat == 0) ? W_ih1 : W_hh1;
        float s0, s1, s2;
        dot3(W, j, hin, b, s0, s1, s2);
        sm[warp][0][b] = s0; sm[warp][1][b] = s1; sm[warp][2][b] = s2;
        __syncthreads();
        if (mat == 0){
            float xr = s0 + b_ih1[j      ];
            float xz = s1 + b_ih1[j+ 512];
            float xn = s2 + b_ih1[j+1024];
            float hr = sm[warp+1][0][b] + b_hh1[j      ];
            float hz = sm[warp+1][1][b] + b_hh1[j+ 512];
            float hn = sm[warp+1][2][b] + b_hh1[j+1024];
            float r = fast_sig(xr + hr);
            float z = fast_sig(xz + hz);
            float n = fast_tanh(xn + r*hn);
            float h1old = g_h1c[p1*BHD + CH(b,j)];
            float hnew = (1.f-z)*n + z*h1old;
            g_h1c[((s+1)&1)*BHD + CH(b,j)] = hnew;
            g_ys[((size_t)s*NB + b)*HD + j] = hnew;
        }
    }
}

// ---------------- final state copy (chunk -> dense) ----------------
__global__ __launch_bounds__(256) void k_fin(float* __restrict__ dout)
{
    int i = blockIdx.x*256 + threadIdx.x;
    if (i >= 2*BHD) return;
    int l = (i >= BHD);
    int r = i & (BHD-1);
    int b = r >> 9, h = r & (HD-1);
    float v = l ? g_h1c[CH(b,h)] : g_h0c[CH(b,h)];   // final parity = 0 (T2 even)
    dout[HF_OFF + i] = v;
}

extern "C" void kernel_launch(void* const* d_in, const int* in_sizes, int n_in,
                              void* d_out, int out_size)
{
    const int*   tok   = (const int*)  d_in[0];
    const float* state = (const float*)d_in[1];
    const float* enc   = (const float*)d_in[2];
    const float* emb   = (const float*)d_in[3];
    const float* wa_W  = (const float*)d_in[4];
    const float* wa_b  = (const float*)d_in[5];
    const float* va_W  = (const float*)d_in[6];
    const float* W_ih0 = (const float*)d_in[7];
    const float* W_hh0 = (const float*)d_in[8];
    const float* b_ih0 = (const float*)d_in[9];
    const float* b_hh0 = (const float*)d_in[10];
    const float* W_ih1 = (const float*)d_in[11];
    const float* W_hh1 = (const float*)d_in[12];
    const float* b_ih1 = (const float*)d_in[13];
    const float* b_hh1 = (const float*)d_in[14];
    const float* out_W = (const float*)d_in[15];
    const float* out_b = (const float*)d_in[16];
    float* dout = (float*)d_out;

    float *pX, *pq, *pep, *pav, *pgi0, *pys;
    cudaGetSymbolAddress((void**)&pX,   g_X);
    cudaGetSymbolAddress((void**)&pq,   g_q);
    cudaGetSymbolAddress((void**)&pep,  g_ep);
    cudaGetSymbolAddress((void**)&pav,  g_av);
    cudaGetSymbolAddress((void**)&pgi0, g_gi0);
    cudaGetSymbolAddress((void**)&pys,  g_ys);

    // 1. embed + state init
    k_embed<<<(TT2*NB*HD + 255)/256, 256>>>(tok, emb, state);

    // 2. enc_proj = enc @ We^T + wa_b      (M=4096, N=512, K=512)
    k_gemm3<<<dim3(HD/64, (TT1*NB)/64), 256>>>(enc, HD, wa_W + HD, 2*HD, wa_b, pep, HD, HD, 0);
    // 3. q = X @ Wx^T                       (M=2048, N=512)
    k_gemm3<<<dim3(HD/64, (TT2*NB)/64), 256>>>(pX, HD, wa_W, 2*HD, nullptr, pq, HD, HD, 0);
    // 4. gi0 = X @ W_ih0[:, :H]^T + b_ih0   (M=2048, N=1536)
    k_gemm3<<<dim3(H3/64, (TT2*NB)/64), 256>>>(pX, HD, W_ih0, 2*HD, b_ih0, pgi0, H3, HD, 0);

    // 5. attention scores + softmax (also writes last_score output)
    k_att_scores<<<dim3(TT2/8, NB), 256>>>(va_W, dout);
    // 6. attention values
    k_attv<<<dim3(NB, TT2/32, HD/256), 256>>>(enc);
    // 7. gi0 += att_v @ W_ih0[:, H:]^T
    k_gemm3<<<dim3(H3/64, (TT2*NB)/64), 256>>>(pav, HD, W_ih0 + HD, 2*HD, nullptr, pgi0, H3, HD, 1);

    // 8. recurrence: pipelined gru0(t) / gru1(t-1)
    for (int t = 0; t <= TT2; t++)
        k_step<<<192, 256>>>(t, W_hh0, b_hh0, W_ih1, b_ih1, W_hh1, b_hh1);

    // 9. y = ys @ out_W^T + out_b           (M=2048, N=32000)
    k_gemm3<<<dim3(VOC/64, (TT2*NB)/64), 256>>>(pys, HD, out_W, HD, out_b, dout, VOC, HD, 0);

    // 10. final hidden states
    k_fin<<<(2*BHD + 255)/256, 256>>>(dout);
    (void)in_sizes; (void)n_in; (void)out_size;
}

// round 4
// speedup vs baseline: 1.9891x; 1.9891x over previous
#include <cuda_runtime.h>
#include <cuda_bf16.h>
#include <cstddef>

#define HD   512
#define VOC  32000
#define TT1  128
#define TT2  64
#define NB   32
#define H3   1536
#define BHD  (NB*HD)
#define YSZ  ((size_t)TT2*NB*VOC)
#define HF_OFF YSZ
#define LS_OFF (YSZ + (size_t)2*BHD)

typedef unsigned int uint_t;

// ---------------- scratch (device globals; no runtime alloc) ----------------
__device__ float g_X  [TT2*NB*HD];      // embedded tokens
__device__ float g_q  [TT2*NB*HD];      // q_all = X @ Wx^T
__device__ float g_ep [TT1*NB*HD];      // enc_proj
__device__ float g_sc [TT2*TT1*NB];     // softmax scores (t2,t1,b)
__device__ float g_av [TT2*NB*HD];      // att_v_all
__device__ float g_gi0[TT2*NB*H3];      // precomputed GRU0 input gates (incl b_ih0)
__device__ float g_ys [TT2*NB*HD];      // h1 per step
__device__ float g_h0c[2*BHD];          // ping-pong layer-0 hidden (chunk layout)
__device__ float g_h1c[2*BHD];          // ping-pong layer-1 hidden (chunk layout)

// bf16-split converted operands: uint2 = (hi_pack(bf16x2), lo_pack(bf16x2)) per 2 floats
__device__ uint2 c_waW [512 * 512];     // wa_W rows, K2=512 (Wx = [,:256], We = [,256:])
__device__ uint2 c_Wih0[H3  * 512];     // W_ih0 rows, K2=512
__device__ uint2 c_outW[(size_t)VOC * 256];
__device__ uint2 c_enc [TT1*NB * 256];
__device__ uint2 c_Xav [TT2*NB * 512];  // [X | att_v] concatenated along K
__device__ uint2 c_ys  [TT2*NB * 256];

// grid barrier state
__device__ unsigned g_bgen = 0;
__device__ unsigned g_bcnt = 0;

// chunk layout: value (b,k) stored at (k>>2)*128 + b*4 + (k&3)
__device__ __forceinline__ int CH(int b, int k){ return ((k>>2)<<7) + (b<<2) + (k&3); }

__device__ __forceinline__ float fast_tanh(float x){
    float e = __expf(2.f*x);
    return 1.f - __fdividef(2.f, e + 1.f);
}
__device__ __forceinline__ float fast_sig(float x){
    return __fdividef(1.f, 1.f + __expf(-x));
}

// ---------------- embed + state init ----------------
__global__ __launch_bounds__(256) void k_embed(const int* __restrict__ tok,
                                               const float* __restrict__ emb,
                                               const float* __restrict__ state)
{
    int i = blockIdx.x*256 + threadIdx.x;
    if (i < TT2*NB*HD){
        int row = i >> 9;
        int h   = i & (HD-1);
        g_X[i] = emb[(size_t)tok[row]*HD + h];
    }
    if (i < 2*BHD){
        int l = (i >= BHD);
        int r = i & (BHD-1);
        int b = r >> 9, h = r & (HD-1);
        float v = state[i];
        if (l == 0) g_h0c[CH(b,h)] = v;
        else        g_h1c[CH(b,h)] = v;
    }
}

// ---------------- fp32 -> bf16 hi/lo split conversion ----------------
__device__ __forceinline__ uint2 splitf2(float x0, float x1){
    __nv_bfloat16 h0 = __float2bfloat16(x0);
    __nv_bfloat16 h1 = __float2bfloat16(x1);
    float r0 = x0 - __bfloat162float(h0);
    float r1 = x1 - __bfloat162float(h1);
    __nv_bfloat16 l0 = __float2bfloat16(r0);
    __nv_bfloat16 l1 = __float2bfloat16(r1);
    uint_t hi = ((uint_t)__bfloat16_as_ushort(h1) << 16) | (uint_t)__bfloat16_as_ushort(h0);
    uint_t lo = ((uint_t)__bfloat16_as_ushort(l1) << 16) | (uint_t)__bfloat16_as_ushort(l0);
    return make_uint2(hi, lo);
}

// one block per row; threads cover K2 columns (stride 256)
__global__ __launch_bounds__(256) void k_conv(const float* __restrict__ src, int lds,
                                              uint2* __restrict__ dst, int K2, int dK2)
{
    int row = blockIdx.x;
    for (int k2 = threadIdx.x; k2 < K2; k2 += 256){
        float2 v = *reinterpret_cast<const float2*>(src + (size_t)row*lds + 2*k2);
        dst[(size_t)row*dK2 + k2] = splitf2(v.x, v.y);
    }
}

// ---------------- bf16-split GEMM: C[M,N] = A(M,K) * B(N,K)^T (+bias) ----------------
__device__ __forceinline__ void mma16(float* d, const uint_t* a, uint_t b0, uint_t b1){
    asm volatile("mma.sync.aligned.m16n8k16.row.col.f32.bf16.bf16.f32 "
        "{%0,%1,%2,%3}, {%4,%5,%6,%7}, {%8,%9}, {%0,%1,%2,%3};\n"
        : "+f"(d[0]), "+f"(d[1]), "+f"(d[2]), "+f"(d[3])
        : "r"(a[0]), "r"(a[1]), "r"(a[2]), "r"(a[3]), "r"(b0), "r"(b1));
}
#define SKB 136   // word stride per k2-plane: 136%32=8 -> conflict-free fragment LDS

__global__ __launch_bounds__(256, 2) void k_gemmbf(
    const uint2* __restrict__ A, int lda2,
    const uint2* __restrict__ B, int ldb2,
    const float* __restrict__ bias,
    float* __restrict__ C, int ldc, int K, int accmode)
{
    __shared__ uint_t sAh[16*SKB], sAl[16*SKB], sBh[16*SKB], sBl[16*SKB];
    const int m0 = blockIdx.y * 128;
    const int n0 = blockIdx.x * 128;
    const int tid = threadIdx.x, lane = tid & 31, warp = tid >> 5;
    const int wm = (warp & 1) * 64;       // warp tile 64(M) x 32(N)
    const int wn = (warp >> 1) * 32;
    const int g  = lane >> 2, tg = lane & 3;

    float acc[4][4][4];
    #pragma unroll
    for (int i=0;i<4;i++)
        #pragma unroll
        for (int j=0;j<4;j++){ acc[i][j][0]=0.f; acc[i][j][1]=0.f; acc[i][j][2]=0.f; acc[i][j][3]=0.f; }

    for (int k0 = 0; k0 < K; k0 += 32){
        const int kh = k0 >> 1;
        #pragma unroll
        for (int i=0;i<4;i++){
            int idx = i*256 + tid;
            int row = idx >> 3, p = idx & 7;
            uint4 va = *reinterpret_cast<const uint4*>(A + (size_t)(m0+row)*lda2 + kh + 2*p);
            sAh[(2*p  )*SKB + row] = va.x;  sAl[(2*p  )*SKB + row] = va.y;
            sAh[(2*p+1)*SKB + row] = va.z;  sAl[(2*p+1)*SKB + row] = va.w;
            uint4 vb = *reinterpret_cast<const uint4*>(B + (size_t)(n0+row)*ldb2 + kh + 2*p);
            sBh[(2*p  )*SKB + row] = vb.x;  sBl[(2*p  )*SKB + row] = vb.y;
            sBh[(2*p+1)*SKB + row] = vb.z;  sBl[(2*p+1)*SKB + row] = vb.w;
        }
        __syncthreads();
        #pragma unroll
        for (int h2=0; h2<2; h2++){
            const int kb2 = h2*8;
            #pragma unroll
            for (int mp=0; mp<2; mp++){
                uint_t ah[2][4], al[2][4];
                #pragma unroll
                for (int q=0;q<2;q++){
                    int rowb  = wm + (mp*2+q)*16 + g;
                    int base0 = (kb2+tg  )*SKB + rowb;
                    int base1 = (kb2+tg+4)*SKB + rowb;
                    ah[q][0]=sAh[base0]; ah[q][1]=sAh[base0+8];
                    ah[q][2]=sAh[base1]; ah[q][3]=sAh[base1+8];
                    al[q][0]=sAl[base0]; al[q][1]=sAl[base0+8];
                    al[q][2]=sAl[base1]; al[q][3]=sAl[base1+8];
                }
                #pragma unroll
                for (int ns=0; ns<4; ns++){
                    int col = wn + ns*8 + g;
                    uint_t bh0 = sBh[(kb2+tg  )*SKB + col];
                    uint_t bh1 = sBh[(kb2+tg+4)*SKB + col];
                    uint_t bl0 = sBl[(kb2+tg  )*SKB + col];
                    uint_t bl1 = sBl[(kb2+tg+4)*SKB + col];
                    #pragma unroll
                    for (int q=0;q<2;q++){
                        float* d = acc[mp*2+q][ns];
                        mma16(d, ah[q], bh0, bh1);   // hi*hi
                        mma16(d, ah[q], bl0, bl1);   // hi*lo
                        mma16(d, al[q], bh0, bh1);   // lo*hi
                    }
                }
            }
        }
        __syncthreads();
    }
    #pragma unroll
    for (int ms=0; ms<4; ms++){
        #pragma unroll
        for (int ns=0; ns<4; ns++){
            int r0  = m0 + wm + ms*16 + g;
            int col = n0 + wn + ns*8 + tg*2;
            float b0v = 0.f, b1v = 0.f;
            if (bias){ b0v = bias[col]; b1v = bias[col+1]; }
            float* p0 = C + (size_t)r0*ldc + col;
            float* p1 = C + (size_t)(r0+8)*ldc + col;
            float c00 = acc[ms][ns][0]+b0v, c01 = acc[ms][ns][1]+b1v;
            float c10 = acc[ms][ns][2]+b0v, c11 = acc[ms][ns][3]+b1v;
            if (accmode){ c00 += p0[0]; c01 += p0[1]; c10 += p1[0]; c11 += p1[1]; }
            p0[0]=c00; p0[1]=c01; p1[0]=c10; p1[1]=c11;
        }
    }
}

// ---------------- attention logits + softmax (t2-group of 8, b) ----------------
__global__ __launch_bounds__(256) void k_att_scores(const float* __restrict__ va,
                                                    float* __restrict__ dout)
{
    __shared__ float q8[8*HD];
    __shared__ float vsm[HD];
    __shared__ float esm[8*TT1];
    const int b   = blockIdx.y;
    const int t2b = blockIdx.x * 8;
    const int tid = threadIdx.x, lane = tid & 31, w = tid >> 5;

    for (int i = tid; i < 8*HD; i += 256){
        int t2i = i >> 9, h = i & (HD-1);
        q8[i] = g_q[((size_t)(t2b + t2i)*NB + b)*HD + h];
    }
    for (int i = tid; i < HD; i += 256) vsm[i] = va[i];
    __syncthreads();

    for (int t1 = w; t1 < TT1; t1 += 8){
        const float* ep = g_ep + ((size_t)t1*NB + b)*HD;
        float accv[8];
        #pragma unroll
        for (int i=0;i<8;i++) accv[i] = 0.f;
        for (int h = lane; h < HD; h += 32){
            float e  = ep[h];
            float vv = vsm[h];
            #pragma unroll
            for (int i=0;i<8;i++) accv[i] += vv * fast_tanh(q8[i*HD + h] + e);
        }
        #pragma unroll
        for (int i=0;i<8;i++){
            float s = accv[i];
            #pragma unroll
            for (int o=16;o;o>>=1) s += __shfl_xor_sync(0xffffffffu, s, o);
            if (lane == 0) esm[i*TT1 + t1] = s;
        }
    }
    __syncthreads();

    {
        float v[4];
        #pragma unroll
        for (int i=0;i<4;i++) v[i] = esm[w*TT1 + lane + 32*i];
        float m = fmaxf(fmaxf(v[0],v[1]), fmaxf(v[2],v[3]));
        #pragma unroll
        for (int o=16;o;o>>=1) m = fmaxf(m, __shfl_xor_sync(0xffffffffu, m, o));
        float s = 0.f;
        #pragma unroll
        for (int i=0;i<4;i++){ v[i] = __expf(v[i]-m); s += v[i]; }
        #pragma unroll
        for (int o=16;o;o>>=1) s += __shfl_xor_sync(0xffffffffu, s, o);
        float inv = __fdividef(1.f, s);
        int t2 = t2b + w;
        #pragma unroll
        for (int i=0;i<4;i++){
            int t1 = lane + 32*i;
            float sc = v[i]*inv;
            g_sc[((size_t)t2*TT1 + t1)*NB + b] = sc;
            if (t2 == TT2-1) dout[LS_OFF + (size_t)t1*NB + b] = sc;
        }
    }
}

// ---------------- attention values ----------------
__global__ __launch_bounds__(256) void k_attv(const float* __restrict__ enc)
{
    __shared__ float sst[TT1*32];
    const int b   = blockIdx.x;
    const int t2o = blockIdx.y * 32;
    const int h   = blockIdx.z * 256 + threadIdx.x;
    for (int i = threadIdx.x; i < 32*TT1; i += 256){
        int t1 = i >> 5, i2 = i & 31;
        sst[t1*32 + i2] = g_sc[((size_t)(t2o + i2)*TT1 + t1)*NB + b];
    }
    __syncthreads();
    float acc[32];
    #pragma unroll
    for (int i=0;i<32;i++) acc[i] = 0.f;
    for (int t1 = 0; t1 < TT1; t1++){
        float ev = enc[((size_t)t1*NB + b)*HD + h];
        #pragma unroll
        for (int i=0;i<32;i++) acc[i] += ev * sst[t1*32 + i];
    }
    #pragma unroll
    for (int i=0;i<32;i++)
        g_av[((size_t)(t2o+i)*NB + b)*HD + h] = acc[i];
}

// ---------------- persistent recurrence ----------------
__device__ __forceinline__ void dot3(const float* __restrict__ W, int j,
                                     const float* __restrict__ hch, int b,
                                     float& s0, float& s1, float& s2)
{
    const float* w0 = W + (size_t) j        *HD;
    const float* w1 = W + (size_t)(j+ 512)  *HD;
    const float* w2 = W + (size_t)(j+1024)  *HD;
    float a0=0.f, a1=0.f, a2=0.f;
    #pragma unroll 4
    for (int k = 0; k < HD; k += 4){
        float4 hv = __ldcg(reinterpret_cast<const float4*>(hch + ((k>>2)<<7) + (b<<2)));
        float4 x = *reinterpret_cast<const float4*>(w0 + k);
        float4 y = *reinterpret_cast<const float4*>(w1 + k);
        float4 z = *reinterpret_cast<const float4*>(w2 + k);
        a0 += x.x*hv.x + x.y*hv.y + x.z*hv.z + x.w*hv.w;
        a1 += y.x*hv.x + y.y*hv.y + y.z*hv.z + y.w*hv.w;
        a2 += z.x*hv.x + z.y*hv.y + z.z*hv.z + z.w*hv.w;
    }
    s0 = a0; s1 = a1; s2 = a2;
}

#define NBLK 192

__global__ __launch_bounds__(256, 2) void k_rec(
    const float* __restrict__ W_hh0, const float* __restrict__ b_hh0,
    const float* __restrict__ W_ih1, const float* __restrict__ b_ih1,
    const float* __restrict__ W_hh1, const float* __restrict__ b_hh1)
{
    const int blk  = blockIdx.x;
    const int warp = threadIdx.x >> 5;
    const int b    = threadIdx.x & 31;
    __shared__ float sm[8][3][32];
    __shared__ unsigned s_gen;
    if (threadIdx.x == 0) s_gen = atomicAdd(&g_bgen, 0u);
    __syncthreads();
    const unsigned G0 = s_gen;

    for (int t = 0; t <= TT2; t++){
        if (blk < 64){
            if (t < TT2){
                const int j = blk*8 + warp;
                const int p = t & 1;
                const float* hch = g_h0c + p*BHD;
                float s0, s1, s2;
                dot3(W_hh0, j, hch, b, s0, s1, s2);
                const float* gi = g_gi0 + ((size_t)t*NB + b)*H3;
                float r = fast_sig (gi[j      ] + s0 + b_hh0[j      ]);
                float z = fast_sig (gi[j+ 512] + s1 + b_hh0[j+ 512]);
                float n = fast_tanh(gi[j+1024] + r*(s2 + b_hh0[j+1024]));
                float hold = __ldcg(&hch[CH(b,j)]);
                __stcg(&g_h0c[(1-p)*BHD + CH(b,j)], (1.f-z)*n + z*hold);
            }
        } else {
            if (t >= 1){
                const int s    = t - 1;
                const int blk2 = blk - 64;
                const int j    = blk2*4 + (warp >> 1);
                const int mat  = warp & 1;
                const int p1   = s & 1;
                const float* hin = (mat == 0) ? (g_h0c + ((s+1)&1)*BHD)
                                              : (g_h1c + p1*BHD);
                const float* W   = (mat == 0) ? W_ih1 : W_hh1;
                float s0, s1, s2;
                dot3(W, j, hin, b, s0, s1, s2);
                sm[warp][0][b] = s0; sm[warp][1][b] = s1; sm[warp][2][b] = s2;
                __syncthreads();
                if (mat == 0){
                    float xr = s0 + b_ih1[j      ];
                    float xz = s1 + b_ih1[j+ 512];
                    float xn = s2 + b_ih1[j+1024];
                    float hr = sm[warp+1][0][b] + b_hh1[j      ];
                    float hz = sm[warp+1][1][b] + b_hh1[j+ 512];
                    float hn = sm[warp+1][2][b] + b_hh1[j+1024];
                    float r = fast_sig(xr + hr);
                    float z = fast_sig(xz + hz);
                    float n = fast_tanh(xn + r*hn);
                    float h1old = __ldcg(&g_h1c[p1*BHD + CH(b,j)]);
                    float hnew = (1.f-z)*n + z*h1old;
                    __stcg(&g_h1c[((s+1)&1)*BHD + CH(b,j)], hnew);
                    g_ys[((size_t)s*NB + b)*HD + j] = hnew;
                }
            }
        }
        if (t == TT2) break;
        // grid barrier
        __syncthreads();
        if (threadIdx.x == 0){
            __threadfence();
            unsigned a = atomicAdd(&g_bcnt, 1u);
            if (a == NBLK-1u){
                atomicExch(&g_bcnt, 0u);
                __threadfence();
                atomicAdd(&g_bgen, 1u);
            } else {
                unsigned target = G0 + (unsigned)t + 1u;
                while ((int)(*(volatile unsigned*)&g_bgen - target) < 0) __nanosleep(64);
            }
            __threadfence();
        }
        __syncthreads();
    }
}

// ---------------- final state copy (chunk -> dense) ----------------
__global__ __launch_bounds__(256) void k_fin(float* __restrict__ dout)
{
    int i = blockIdx.x*256 + threadIdx.x;
    if (i >= 2*BHD) return;
    int l = (i >= BHD);
    int r = i & (BHD-1);
    int b = r >> 9, h = r & (HD-1);
    float v = l ? g_h1c[CH(b,h)] : g_h0c[CH(b,h)];   // final parity = 0 (T2 even)
    dout[HF_OFF + i] = v;
}

extern "C" void kernel_launch(void* const* d_in, const int* in_sizes, int n_in,
                              void* d_out, int out_size)
{
    const int*   tok   = (const int*)  d_in[0];
    const float* state = (const float*)d_in[1];
    const float* enc   = (const float*)d_in[2];
    const float* emb   = (const float*)d_in[3];
    const float* wa_W  = (const float*)d_in[4];
    const float* wa_b  = (const float*)d_in[5];
    const float* va_W  = (const float*)d_in[6];
    const float* W_ih0 = (const float*)d_in[7];
    const float* W_hh0 = (const float*)d_in[8];
    const float* b_ih0 = (const float*)d_in[9];
    const float* b_hh0 = (const float*)d_in[10];
    const float* W_ih1 = (const float*)d_in[11];
    const float* W_hh1 = (const float*)d_in[12];
    const float* b_ih1 = (const float*)d_in[13];
    const float* b_hh1 = (const float*)d_in[14];
    const float* out_W = (const float*)d_in[15];
    const float* out_b = (const float*)d_in[16];
    float* dout = (float*)d_out;

    float *pX, *pep, *pq, *pav, *pgi0, *pys;
    uint2 *pcwaW, *pcWih0, *pcoutW, *pcenc, *pcXav, *pcys;
    cudaGetSymbolAddress((void**)&pX,    g_X);
    cudaGetSymbolAddress((void**)&pep,   g_ep);
    cudaGetSymbolAddress((void**)&pq,    g_q);
    cudaGetSymbolAddress((void**)&pav,   g_av);
    cudaGetSymbolAddress((void**)&pgi0,  g_gi0);
    cudaGetSymbolAddress((void**)&pys,   g_ys);
    cudaGetSymbolAddress((void**)&pcwaW, c_waW);
    cudaGetSymbolAddress((void**)&pcWih0,c_Wih0);
    cudaGetSymbolAddress((void**)&pcoutW,c_outW);
    cudaGetSymbolAddress((void**)&pcenc, c_enc);
    cudaGetSymbolAddress((void**)&pcXav, c_Xav);
    cudaGetSymbolAddress((void**)&pcys,  c_ys);

    // 1. embed + state init
    k_embed<<<(TT2*NB*HD + 255)/256, 256>>>(tok, emb, state);

    // 2. operand conversions (weights + enc + X)
    k_conv<<<512,  256>>>(wa_W,  2*HD, pcwaW,  512, 512);
    k_conv<<<H3,   256>>>(W_ih0, 2*HD, pcWih0, 512, 512);
    k_conv<<<VOC,  256>>>(out_W, HD,   pcoutW, 256, 256);
    k_conv<<<TT1*NB, 256>>>(enc, HD,   pcenc,  256, 256);
    k_conv<<<TT2*NB, 256>>>(pX,  HD,   pcXav,  256, 512);

    // 3. enc_proj = enc @ We^T + wa_b    (M=4096, N=512, K=512)
    k_gemmbf<<<dim3(HD/128, (TT1*NB)/128), 256>>>(pcenc, 256, pcwaW + 256, 512, wa_b, pep, HD, HD, 0);
    // 4. q = X @ Wx^T                    (M=2048, N=512, K=512)
    k_gemmbf<<<dim3(HD/128, (TT2*NB)/128), 256>>>(pcXav, 512, pcwaW, 512, nullptr, pq, HD, HD, 0);

    // 5. attention scores + softmax (writes last_score)
    k_att_scores<<<dim3(TT2/8, NB), 256>>>(va_W, dout);
    // 6. attention values
    k_attv<<<dim3(NB, TT2/32, HD/256), 256>>>(enc);
    // 7. convert att_v into c_Xav[:, 256:]
    k_conv<<<TT2*NB, 256>>>(pav, HD, pcXav + 256, 256, 512);
    // 8. gi0 = [X, att_v] @ W_ih0^T + b_ih0   (M=2048, N=1536, K=1024)
    k_gemmbf<<<dim3(H3/128, (TT2*NB)/128), 256>>>(pcXav, 512, pcWih0, 512, b_ih0, pgi0, H3, 2*HD, 0);

    // 9. persistent recurrence (both GRU layers, pipelined)
    k_rec<<<NBLK, 256>>>(W_hh0, b_hh0, W_ih1, b_ih1, W_hh1, b_hh1);

    // 10. y = ys @ out_W^T + out_b      (M=2048, N=32000, K=512)
    k_conv<<<TT2*NB, 256>>>(pys, HD, pcys, 256, 256);
    k_gemmbf<<<dim3(VOC/128, (TT2*NB)/128), 256>>>(pcys, 256, pcoutW, 256, out_b, dout, VOC, HD, 0);

    // 11. final hidden states
    k_fin<<<(2*BHD + 255)/256, 256>>>(dout);
    (void)in_sizes; (void)n_in; (void)out_size; (void)W_ih0;
}